// round 3
// baseline (speedup 1.0000x reference)
#include <cuda_runtime.h>
#include <math.h>

#define D_IN      40
#define WID       128
#define NSEG      2048
#define NHEADS    4
#define MAXN      500000
#define TILE      128
#define ENC_T     1024
#define HSTR      132

typedef unsigned long long ull;

// ---------------------------------------------------------------------------
__device__ __align__(16) float g_segSum[NSEG * WID];
__device__ float g_segCnt[NSEG];
__device__ __align__(16) float g_t[NSEG * NHEADS];
__device__ __align__(16) float g_den[NSEG * NHEADS];
__device__ __align__(16) float g_V[(D_IN + WID) * NHEADS];
__device__ __align__(16) float g_P[MAXN * NHEADS];

// ---------------------------------------------------------------------------
__device__ __forceinline__ ull ffma2(ull a, ull b, ull c) {
    ull d;
    asm("fma.rn.f32x2 %0, %1, %2, %3;" : "=l"(d) : "l"(a), "l"(b), "l"(c));
    return d;
}
__device__ __forceinline__ ull pack2(float x) {
    ull d;
    asm("mov.b64 %0, {%1, %1};" : "=l"(d) : "f"(x));
    return d;
}
__device__ __forceinline__ void unpack2(ull v, float& lo, float& hi) {
    asm("mov.b64 {%0, %1}, %2;" : "=f"(lo), "=f"(hi) : "l"(v));
}

// ---------------------------------------------------------------------------
__global__ void k_zero() {
    int i = blockIdx.x * blockDim.x + threadIdx.x;
    int stride = gridDim.x * blockDim.x;
    for (int j = i; j < NSEG * WID; j += stride) g_segSum[j] = 0.f;
    for (int j = i; j < NSEG; j += stride) g_segCnt[j] = 0.f;
    for (int j = i; j < NSEG * NHEADS; j += stride) { g_den[j] = 0.f; g_t[j] = 0.f; }
}

__global__ void k_fold(const float* __restrict__ Wk, const float* __restrict__ Wq) {
    int i = threadIdx.x;
    if (i < (D_IN + WID) * NHEADS) {
        int d = i >> 2, h = i & 3;
        float s = 0.f;
        const float* wk = Wk + d * 256 + h * 64;
        const float* wq = Wq + h * 64;
#pragma unroll 8
        for (int k = 0; k < 64; k++) s += wk[k] * wq[k];
        g_V[i] = s;
    }
}

// ---------------------------------------------------------------------------
// Encoder: 1024 threads. Warp w: cols c0 = (w&15)*8; rows half rh = w>>4.
// Lane: rows r0 = rh*64 + lane*2.  Thread tile: 2 rows x 8 cols, f32x2 FMA.
// SMEM float layout:
//  sV: 0 (160) | sW1: 160 (5120) | sB1: 5280 sB2: 5408 sB3: 5536 |
//  sW2: 5664 (16384) | sW3: 22048 (16384) | sH: 38432 (128*HSTR=16896) |
//  sSeg: 55328 (128)
#define ENC_SMEM_FLOATS 55456
#define ENC_SMEM_BYTES  (ENC_SMEM_FLOATS * 4)

template <int K>
__device__ __forceinline__ void layerT2(const float* __restrict__ At,
                                        const float* __restrict__ W,
                                        int c0, int r0, ull acc[2][4]) {
#pragma unroll
    for (int r = 0; r < 2; r++)
#pragma unroll
        for (int j = 0; j < 4; j++) acc[r][j] = 0ULL;
#pragma unroll 2
    for (int k = 0; k < K; k++) {
        float2 xv = *reinterpret_cast<const float2*>(At + k * HSTR + r0);
        ull x0 = pack2(xv.x), x1 = pack2(xv.y);
        ulonglong2 wa = *reinterpret_cast<const ulonglong2*>(W + k * WID + c0);
        ulonglong2 wb = *reinterpret_cast<const ulonglong2*>(W + k * WID + c0 + 4);
        acc[0][0] = ffma2(x0, wa.x, acc[0][0]); acc[0][1] = ffma2(x0, wa.y, acc[0][1]);
        acc[0][2] = ffma2(x0, wb.x, acc[0][2]); acc[0][3] = ffma2(x0, wb.y, acc[0][3]);
        acc[1][0] = ffma2(x1, wa.x, acc[1][0]); acc[1][1] = ffma2(x1, wa.y, acc[1][1]);
        acc[1][2] = ffma2(x1, wb.x, acc[1][2]); acc[1][3] = ffma2(x1, wb.y, acc[1][3]);
    }
}

__device__ __forceinline__ void storeT2(float* __restrict__ Ht,
                                        const float* __restrict__ bias,
                                        int c0, int r0, ull acc[2][4]) {
#pragma unroll
    for (int j = 0; j < 4; j++) {
        int c = c0 + 2 * j;
        float bl = bias[c], bh = bias[c + 1];
        float l0, h0, l1, h1;
        unpack2(acc[0][j], l0, h0);
        unpack2(acc[1][j], l1, h1);
        float2 v;
        v.x = fmaxf(l0 + bl, 0.f); v.y = fmaxf(l1 + bl, 0.f);
        *reinterpret_cast<float2*>(Ht + c * HSTR + r0) = v;
        v.x = fmaxf(h0 + bh, 0.f); v.y = fmaxf(h1 + bh, 0.f);
        *reinterpret_cast<float2*>(Ht + (c + 1) * HSTR + r0) = v;
    }
}

__global__ void __launch_bounds__(ENC_T, 1)
k_encoder(const float* __restrict__ X, const int* __restrict__ seg,
          const float* __restrict__ W1, const float* __restrict__ b1,
          const float* __restrict__ W2, const float* __restrict__ b2,
          const float* __restrict__ W3, const float* __restrict__ b3,
          int N, int numTiles) {
    extern __shared__ float sm[];
    float* sV  = sm;
    float* sW1 = sm + 160;
    float* sB1 = sm + 5280;
    float* sB2 = sm + 5408;
    float* sB3 = sm + 5536;
    float* sW2 = sm + 5664;
    float* sW3 = sm + 22048;
    float* sH  = sm + 38432;
    int*   sSeg = (int*)(sm + 55328);

    const unsigned full = 0xffffffffu;
    int tid = threadIdx.x;
    int wid = tid >> 5;
    int lane = tid & 31;
    int c0 = (wid & 15) * 8;
    int rh = wid >> 4;
    int r0 = rh * 64 + lane * 2;

    for (int i = tid; i < D_IN * NHEADS; i += ENC_T) sV[i] = g_V[i];
    for (int i = tid; i < 5120; i += ENC_T) sW1[i] = W1[i];
    for (int i = tid; i < 128; i += ENC_T) { sB1[i] = b1[i]; sB2[i] = b2[i]; sB3[i] = b3[i]; }
    for (int i = tid; i < 16384; i += ENC_T) { sW2[i] = W2[i]; sW3[i] = W3[i]; }

    ull acc[2][4];

    for (int tile = blockIdx.x; tile < numTiles; tile += gridDim.x) {
        int row0 = tile * TILE;

        __syncthreads();  // (A) prev tile's sH/sSeg readers done

        // stage X transposed (coalesced global read)
        for (int i = tid; i < TILE * D_IN; i += ENC_T) {
            int r = i / D_IN, d = i - r * D_IN;
            int g = row0 + r;
            sH[d * HSTR + r] = (g < N) ? X[g * D_IN + d] : 0.f;
        }
        if (tid < TILE) sSeg[tid] = (row0 + tid < N) ? seg[row0 + tid] : -1;
        __syncthreads();  // (B)

        // partial logits: task = (row, head), 2 threads split d-range
        {
            int r = tid >> 3, h = (tid >> 1) & 3, half = tid & 1;
            float p = 0.f;
            int d0 = half * 20;
#pragma unroll
            for (int d = 0; d < 20; d++) p += sH[(d0 + d) * HSTR + r] * sV[(d0 + d) * 4 + h];
            p += __shfl_xor_sync(full, p, 1);
            int n = row0 + r;
            if (half == 0 && n < N) g_P[n * 4 + h] = p;
        }

        // layer 1
        layerT2<D_IN>(sH, sW1, c0, r0, acc);
        __syncthreads();  // (C) sX reads done
        storeT2(sH, sB1, c0, r0, acc);
        __syncthreads();  // (D)
        // layer 2
        layerT2<WID>(sH, sW2, c0, r0, acc);
        __syncthreads();  // (E)
        storeT2(sH, sB2, c0, r0, acc);
        __syncthreads();  // (F)
        // layer 3: keep in regs
        layerT2<WID>(sH, sW3, c0, r0, acc);

        float v0[8], v1[8];
#pragma unroll
        for (int j = 0; j < 4; j++) {
            int c = c0 + 2 * j;
            float bl = sB3[c], bh = sB3[c + 1];
            float l0, h0, l1, h1;
            unpack2(acc[0][j], l0, h0);
            unpack2(acc[1][j], l1, h1);
            v0[2 * j] = fmaxf(l0 + bl, 0.f); v0[2 * j + 1] = fmaxf(h0 + bh, 0.f);
            v1[2 * j] = fmaxf(l1 + bl, 0.f); v1[2 * j + 1] = fmaxf(h1 + bh, 0.f);
        }

        // segment-sum from registers: run-loop over distinct segments
        {
            int sA = sSeg[r0];
            int sB = sSeg[r0 + 1];
            const int INF = 0x7fffffff;
            int t = min(sA < 0 ? INF : sA, sB < 0 ? INF : sB);
#pragma unroll
            for (int off = 16; off; off >>= 1) t = min(t, __shfl_xor_sync(full, t, off));
            while (t != INF) {
                float s[8];
#pragma unroll
                for (int c = 0; c < 8; c++) {
                    float a = (sA == t) ? v0[c] : 0.f;
                    if (sB == t) a += v1[c];
                    s[c] = a;
                }
#pragma unroll
                for (int off = 16; off; off >>= 1)
#pragma unroll
                    for (int c = 0; c < 8; c++) s[c] += __shfl_xor_sync(full, s[c], off);
                if (lane == 0) {
                    float* dst = &g_segSum[t * WID + c0];
                    atomicAdd(dst + 0, s[0]); atomicAdd(dst + 1, s[1]);
                    atomicAdd(dst + 2, s[2]); atomicAdd(dst + 3, s[3]);
                    atomicAdd(dst + 4, s[4]); atomicAdd(dst + 5, s[5]);
                    atomicAdd(dst + 6, s[6]); atomicAdd(dst + 7, s[7]);
                }
                int nA = (sA > t) ? sA : INF;
                int nB = (sB > t) ? sB : INF;
                int nt = min(nA, nB);
#pragma unroll
                for (int off = 16; off; off >>= 1) nt = min(nt, __shfl_xor_sync(full, nt, off));
                t = nt;
            }
        }

        // counts: warp 0, lane covers rows lane*4..lane*4+3
        if (wid == 0) {
            int s0 = sSeg[lane * 4 + 0], s1 = sSeg[lane * 4 + 1];
            int s2 = sSeg[lane * 4 + 2], s3 = sSeg[lane * 4 + 3];
            const int INF = 0x7fffffff;
            int t = min(min(s0 < 0 ? INF : s0, s1 < 0 ? INF : s1),
                        min(s2 < 0 ? INF : s2, s3 < 0 ? INF : s3));
#pragma unroll
            for (int off = 16; off; off >>= 1) t = min(t, __shfl_xor_sync(full, t, off));
            while (t != INF) {
                float cnt = (s0 == t) + (s1 == t) + (s2 == t) + (s3 == t);
#pragma unroll
                for (int off = 16; off; off >>= 1) cnt += __shfl_xor_sync(full, cnt, off);
                if (lane == 0) atomicAdd(&g_segCnt[t], cnt);
                int n0 = (s0 > t) ? s0 : INF, n1 = (s1 > t) ? s1 : INF;
                int n2 = (s2 > t) ? s2 : INF, n3 = (s3 > t) ? s3 : INF;
                int nt = min(min(n0, n1), min(n2, n3));
#pragma unroll
                for (int off = 16; off; off >>= 1) nt = min(nt, __shfl_xor_sync(full, nt, off));
                t = nt;
            }
        }
    }
}

// ---------------------------------------------------------------------------
// rho: 128 blocks x 16 segments, Wr staged in smem
#define RHO_SEGS 16
__global__ void __launch_bounds__(WID, 1)
k_rho(const float* __restrict__ Wr, const float* __restrict__ br) {
    extern __shared__ float sWr[];
    __shared__ float sMean[RHO_SEGS][WID];
    __shared__ float sAgg[RHO_SEGS][WID];

    int c = threadIdx.x;
    int s0 = blockIdx.x * RHO_SEGS;

    for (int i = c; i < WID * WID; i += WID) sWr[i] = Wr[i];
    for (int i = 0; i < RHO_SEGS; i++) {
        float cnt = g_segCnt[s0 + i];
        float inv = 1.f / fmaxf(cnt, 1.f);
        sMean[i][c] = g_segSum[(s0 + i) * WID + c] * inv;
    }
    __syncthreads();

    float a[RHO_SEGS];
#pragma unroll
    for (int i = 0; i < RHO_SEGS; i++) a[i] = br[c];
#pragma unroll 4
    for (int k = 0; k < WID; k++) {
        float w = sWr[k * WID + c];
#pragma unroll
        for (int i = 0; i < RHO_SEGS; i++) a[i] += sMean[i][k] * w;
    }
#pragma unroll
    for (int i = 0; i < RHO_SEGS; i++) sAgg[i][c] = fmaxf(a[i], 0.f);
    __syncthreads();

    if (c < RHO_SEGS * NHEADS * 2) {
        int pair = c >> 1, half = c & 1;
        int si = pair >> 2, h = pair & 3;
        float t = 0.f;
#pragma unroll 8
        for (int k = half * 64; k < half * 64 + 64; k++)
            t += sAgg[si][k] * g_V[(D_IN + k) * 4 + h];
        atomicAdd(&g_t[(s0 + si) * 4 + h], t);
    }
}

// ---------------------------------------------------------------------------
__global__ void k_attn(const int* __restrict__ seg, int N) {
    int n = blockIdx.x * 256 + threadIdx.x;
    bool ok = (n < N);
    int sg = ok ? seg[n] : -1;
    int sgl = (sg >= 0) ? sg : 0;

    float4 p = ok ? *reinterpret_cast<const float4*>(&g_P[n * 4]) : make_float4(0, 0, 0, 0);
    float4 t = *reinterpret_cast<const float4*>(&g_t[sgl * 4]);
    const float sc = 0.125f;
    float e0 = ok ? __expf((p.x + t.x) * sc) : 0.f;
    float e1 = ok ? __expf((p.y + t.y) * sc) : 0.f;
    float e2 = ok ? __expf((p.z + t.z) * sc) : 0.f;
    float e3 = ok ? __expf((p.w + t.w) * sc) : 0.f;

    if (ok) *reinterpret_cast<float4*>(&g_P[n * 4]) = make_float4(e0, e1, e2, e3);

    unsigned full = 0xffffffffu;
    int lane = threadIdx.x & 31;
    int sg0 = __shfl_sync(full, sg, 0);
    bool uni = __all_sync(full, sg == sg0);
    if (uni) {
        float r0 = e0, r1 = e1, r2 = e2, r3 = e3;
#pragma unroll
        for (int off = 16; off > 0; off >>= 1) {
            r0 += __shfl_down_sync(full, r0, off);
            r1 += __shfl_down_sync(full, r1, off);
            r2 += __shfl_down_sync(full, r2, off);
            r3 += __shfl_down_sync(full, r3, off);
        }
        if (lane == 0 && sg0 >= 0) {
            atomicAdd(&g_den[sg0 * 4 + 0], r0); atomicAdd(&g_den[sg0 * 4 + 1], r1);
            atomicAdd(&g_den[sg0 * 4 + 2], r2); atomicAdd(&g_den[sg0 * 4 + 3], r3);
        }
    } else if (sg >= 0) {
        atomicAdd(&g_den[sg * 4 + 0], e0); atomicAdd(&g_den[sg * 4 + 1], e1);
        atomicAdd(&g_den[sg * 4 + 2], e2); atomicAdd(&g_den[sg * 4 + 3], e3);
    }
}

__global__ void k_norm(const int* __restrict__ seg, float* __restrict__ out, int N) {
    int n = blockIdx.x * 256 + threadIdx.x;
    if (n >= N) return;
    float4 e = *reinterpret_cast<const float4*>(&g_P[n * 4]);
    int s = seg[n];
    float4 d = *reinterpret_cast<const float4*>(&g_den[s * 4]);
    out[0 * N + n] = e.x / d.x;
    out[1 * N + n] = e.y / d.y;
    out[2 * N + n] = e.z / d.z;
    out[3 * N + n] = e.w / d.w;
}

// ---------------------------------------------------------------------------
extern "C" void kernel_launch(void* const* d_in, const int* in_sizes, int n_in,
                              void* d_out, int out_size) {
    const float* X  = (const float*)d_in[0];
    const int*   sg = (const int*)d_in[1];
    const float* W1 = (const float*)d_in[3];
    const float* b1 = (const float*)d_in[4];
    const float* W2 = (const float*)d_in[5];
    const float* b2 = (const float*)d_in[6];
    const float* W3 = (const float*)d_in[7];
    const float* b3 = (const float*)d_in[8];
    const float* Wr = (const float*)d_in[9];
    const float* br = (const float*)d_in[10];
    const float* Wk = (const float*)d_in[11];
    const float* Wq = (const float*)d_in[12];
    float* out = (float*)d_out;

    int N = in_sizes[0] / D_IN;
    int tiles = (N + TILE - 1) / TILE;

    cudaFuncSetAttribute(k_encoder, cudaFuncAttributeMaxDynamicSharedMemorySize, ENC_SMEM_BYTES);
    cudaFuncSetAttribute(k_rho, cudaFuncAttributeMaxDynamicSharedMemorySize, WID * WID * 4);

    k_zero<<<64, 256>>>();
    k_fold<<<1, (D_IN + WID) * NHEADS>>>(Wk, Wq);
    k_encoder<<<148, ENC_T, ENC_SMEM_BYTES>>>(X, sg, W1, b1, W2, b2, W3, b3, N, tiles);
    k_rho<<<NSEG / RHO_SEGS, WID, WID * WID * 4>>>(Wr, br);
    k_attn<<<(N + 255) / 256, 256>>>(sg, N);
    k_norm<<<(N + 255) / 256, 256>>>(sg, out, N);
}